// round 15
// baseline (speedup 1.0000x reference)
#include <cuda_runtime.h>
#include <cuda_fp16.h>
#include <cstdint>

// ============================================================================
// LatentQuantizer: persistent-CTA two-pass fp16 HMMA distance GEMM with
// fp16 ACCUMULATORS (2x HMMA rate if the pipe supports it).
// Pass 1: branchless per-row max-dot D via HMAX2.
// Pass 2: branch-cold push gated by one __hble2 per result register.
// Margin widened (2^-7) to rigorously cover fp16 accumulation error.
// Exact fp32 lexicographic refine; rare overflow -> full fp32 fallback.
// Inputs: latents [N*64] f32, scaler [N] f32, redshift [N] f32,
//         codebook_weight [64*1024] f32 (D-major).
// Output f32: z_q_st [N*64], scaler [N], redshift [N], loss [1], ids [N]
// ============================================================================

#define DIMS   64
#define NEMB   1024
#define MTILE  256          // rows per tile
#define TPB    512          // 16 warps, 16 rows/warp
#define CAP    8            // candidate index slots per row
#define NCTAS  148          // persistent grid (1 CTA/SM)

// dynamic smem layout (bytes)
#define SM_B     0                           // 1024 x 128B fp16 swizzled (resident)
#define SM_A     (SM_B + NEMB * 128)         // 131072: 256 x 128B
#define SM_ZN    (SM_A + MTILE * 128)        // 163840: 256 f32
#define SM_CE    (SM_ZN + MTILE * 4)         // 164864: 256 x CAP ints
#define SM_CNT   (SM_CE + MTILE * CAP * 4)   // 173056: 256 ints
#define SM_WSUM  (SM_CNT + MTILE * 4)        // 174080: 16 f32
#define SM_TOTAL (SM_WSUM + 64)              // 174144

#define FB_CAP (1 << 19)

// -------------------- device scratch (no allocations) -----------------------
__device__ __align__(16)   float  g_Wtf[NEMB * DIMS];   // e-major fp32
__device__ __align__(1024) __half g_Wth[NEMB * DIMS];   // e-major fp16, swizzled
__device__ float  g_wnorm[NEMB];
__device__ int    g_wmaxbits = 0;
__device__ int    g_wminbits = 0x7f7fffff;
__device__ double g_loss;
__device__ int    g_nfb;
__device__ int    g_fbrows[FB_CAP];

__device__ __forceinline__ uint32_t sw128(uint32_t o) { return o ^ ((o >> 3) & 0x70); }

__device__ __forceinline__ uint32_t smem_u32(const void* p) {
    uint32_t a;
    asm("{ .reg .u64 t; cvta.to.shared.u64 t, %1; cvt.u32.u64 %0, t; }"
        : "=r"(a) : "l"(p));
    return a;
}

#define LDSM_X4(r, addr)                                                     \
    asm volatile("ldmatrix.sync.aligned.m8n8.x4.shared.b16 {%0,%1,%2,%3}, [%4];" \
        : "=r"((r)[0]), "=r"((r)[1]), "=r"((r)[2]), "=r"((r)[3])             \
        : "r"(addr))

// fp16-accumulator HMMA: D/C are 2 packed half2 registers.
__device__ __forceinline__ void mma_h(uint32_t* d, const uint32_t* a,
                                      const uint32_t* b) {
    asm volatile(
        "mma.sync.aligned.m16n8k16.row.col.f16.f16.f16.f16 "
        "{%0,%1}, {%2,%3,%4,%5}, {%6,%7}, {%0,%1};"
        : "+r"(d[0]), "+r"(d[1])
        : "r"(a[0]), "r"(a[1]), "r"(a[2]), "r"(a[3]), "r"(b[0]), "r"(b[1]));
}

// ============================================================================
// prep: wnorm + min/max, fp32 transpose, swizzled fp16 transpose, zero accums
// ============================================================================
__global__ void prep_kernel(const float* __restrict__ W) {
    int e = blockIdx.x * blockDim.x + threadIdx.x;
    if (blockIdx.x == 0 && threadIdx.x == 0) { g_loss = 0.0; g_nfb = 0; }
    if (e >= NEMB) return;
    float col[DIMS];
    float s = 0.f;
    #pragma unroll
    for (int d = 0; d < DIMS; ++d) {
        float v = W[d * NEMB + e];
        col[d] = v;
        s = fmaf(v, v, s);
    }
    g_wnorm[e] = s;
    atomicMax(&g_wmaxbits, __float_as_int(s));   // s > 0: int order == float
    atomicMin(&g_wminbits, __float_as_int(s));
    float4* dst = (float4*)(g_Wtf + (size_t)e * DIMS);
    #pragma unroll
    for (int i = 0; i < DIMS / 4; ++i)
        dst[i] = make_float4(col[4*i], col[4*i+1], col[4*i+2], col[4*i+3]);
    char* bb = (char*)g_Wth;
    #pragma unroll
    for (int k = 0; k < DIMS; k += 2) {
        __half2 p = __floats2half2_rn(col[k], col[k + 1]);
        uint32_t bo = (uint32_t)e * 128u + (uint32_t)k * 2u;
        *(uint32_t*)(bb + sw128(bo)) = *(uint32_t*)&p;
    }
}

// ============================================================================
// vq: persistent CTAs; B resident; per-tile two-pass (max-dot, then push).
// ============================================================================
__global__ __launch_bounds__(TPB, 1) void vq_kernel(
    const float* __restrict__ latents,
    const float* __restrict__ scaler,
    const float* __restrict__ redshift,
    float* __restrict__ out,
    int N)
{
    extern __shared__ char smem[];
    const uint32_t sb = smem_u32(smem);
    const int tid = threadIdx.x, wid = tid >> 5, lane = tid & 31;

    float* szn  = (float*)(smem + SM_ZN);
    int*   sce  = (int*)(smem + SM_CE);
    int*   scnt = (int*)(smem + SM_CNT);

    // ---- B: full fp16 codebook -> smem ONCE (pre-swizzled, raw copy) ----
    {
        const float4* src = (const float4*)g_Wth;
        float4* dst = (float4*)(smem + SM_B);
        #pragma unroll 8
        for (int i = tid; i < NEMB * 128 / 16; i += TPB) dst[i] = src[i];
    }

    const float wmax = __int_as_float(g_wmaxbits);
    const float wrange = wmax - __int_as_float(g_wminbits);

    const uint32_t brow = sb + SM_B + (lane & 7) * 128;
    const uint32_t bx1  = (((lane >> 3) ^ (lane & 7)) << 4);
    const uint32_t bx2  = ((((lane >> 3) + 4) ^ (lane & 7)) << 4);
    const int cbase = (lane & 3) * 2;
    const int wb = wid * 16;                 // 16 rows per warp

    const int ntiles = (N + MTILE - 1) / MTILE;
    float lacc = 0.f;                        // per-thread loss across tiles

    for (int tile = blockIdx.x; tile < ntiles; tile += gridDim.x) {
        const long long row0 = (long long)tile * MTILE;
        __syncthreads();                     // prior tile epilogue done

        // ---- per-tile prologue: reset counters, A convert + ||z||^2 ----
        for (int i = tid; i < MTILE; i += TPB) scnt[i] = 0;
        for (int i = tid; i < MTILE * 32; i += TPB) {
            int r = i >> 5, kp = i & 31;     // whole warp shares r
            long long gr = row0 + r;
            float2 z2 = (gr < N) ? ((const float2*)latents)[gr * 32 + kp]
                                 : make_float2(0.f, 0.f);
            __half2 p = __floats2half2_rn(z2.x, z2.y);
            *(uint32_t*)(smem + SM_A + sw128((uint32_t)r * 128u + (uint32_t)kp * 4u))
                = *(uint32_t*)&p;
            float zp = fmaf(z2.x, z2.x, z2.y * z2.y);
            #pragma unroll
            for (int o = 16; o > 0; o >>= 1)
                zp += __shfl_down_sync(0xffffffffu, zp, o);
            if (lane == 0) szn[r] = zp;
        }
        __syncthreads();

        // ---- A fragments: 1 m16 tile x 4 k16 steps (16 regs) ----
        uint32_t afrag[4][4];
        {
            int rr = wb + ((lane >> 3) & 1) * 8 + (lane & 7);
            #pragma unroll
            for (int ks = 0; ks < 4; ++ks) {
                int kb = ks * 2 + (lane >> 4);
                uint32_t ad = sb + SM_A + rr * 128 + ((kb ^ (rr & 7)) << 4);
                LDSM_X4(afrag[ks], ad);
            }
        }

        // ========= pass 1: running max dot via HMAX2 (branchless) =========
        __half2 M0 = __half2half2(__ushort_as_half(0xFC00));   // -inf
        __half2 M1 = M0;
        #pragma unroll 2
        for (int nt = 0; nt < NEMB / 8; ++nt) {
            const int n0 = nt * 8;
            uint32_t b[8];
            LDSM_X4(b,     brow + n0 * 128 + bx1);
            LDSM_X4(b + 4, brow + n0 * 128 + bx2);
            uint32_t dd[2] = {0u, 0u};
            #pragma unroll
            for (int ks = 0; ks < 4; ++ks)
                mma_h(dd, afrag[ks], b + 2 * ks);
            M0 = __hmax2(M0, *(__half2*)&dd[0]);
            M1 = __hmax2(M1, *(__half2*)&dd[1]);
        }
        float D0 = fmaxf(__low2float(M0), __high2float(M0));
        float D1 = fmaxf(__low2float(M1), __high2float(M1));
        // quad merge (4 lanes sharing each row)
        D0 = fmaxf(D0, __shfl_xor_sync(0xffffffffu, D0, 1));
        D0 = fmaxf(D0, __shfl_xor_sync(0xffffffffu, D0, 2));
        D1 = fmaxf(D1, __shfl_xor_sync(0xffffffffu, D1, 1));
        D1 = fmaxf(D1, __shfl_xor_sync(0xffffffffu, D1, 2));

        // thresholds: t = D - 0.5*wrange - 2eps, eps <= 2^-8*sqrt(zn*wmax)
        // (operand 2^-10 + fp16-accum 4*2^-11, doubled for safety -> 2^-7 coeff)
        const int rl0 = wb + (lane >> 2), rl1 = rl0 + 8;
        const float t0 = D0 - 0.5f * wrange
                       - 0.0078125f * sqrtf(szn[rl0] * wmax) - 1e-4f;
        const float t1 = D1 - 0.5f * wrange
                       - 0.0078125f * sqrtf(szn[rl1] * wmax) - 1e-4f;
        // half2 gate thresholds, rounded DOWN so the gate never rejects a
        // candidate the float compare would accept
        const float t0a = t0 - (fabsf(t0) * 2e-3f + 1e-6f);
        const float t1a = t1 - (fabsf(t1) * 2e-3f + 1e-6f);
        const __half2 t0h = __float2half2_rn(t0a);
        const __half2 t1h = __float2half2_rn(t1a);

        // ========= pass 2: branch-cold candidate pushes =========
#define PUSH(RL, E) do {                                                      \
            int _s = atomicAdd(&scnt[RL], 1);                                 \
            if (_s < CAP) sce[(RL) * CAP + _s] = (E);                         \
        } while (0)

        #pragma unroll 2
        for (int nt = 0; nt < NEMB / 8; ++nt) {
            const int n0 = nt * 8;
            uint32_t b[8];
            LDSM_X4(b,     brow + n0 * 128 + bx1);
            LDSM_X4(b + 4, brow + n0 * 128 + bx2);
            uint32_t dd[2] = {0u, 0u};
            #pragma unroll
            for (int ks = 0; ks < 4; ++ks)
                mma_h(dd, afrag[ks], b + 2 * ks);
            const int c0 = n0 + cbase, c1 = c0 + 1;
            __half2 h0 = *(__half2*)&dd[0];
            __half2 h1 = *(__half2*)&dd[1];
            if (!__hble2(h0, t0h)) {         // any(h0 > t0h) -- rare
                float da = __low2float(h0), db = __high2float(h0);
                if (da > t0) PUSH(rl0, c0);
                if (db > t0) PUSH(rl0, c1);
            }
            if (!__hble2(h1, t1h)) {
                float da = __low2float(h1), db = __high2float(h1);
                if (da > t1) PUSH(rl1, c0);
                if (db > t1) PUSH(rl1, c1);
            }
        }
#undef PUSH
        __syncthreads();

        // ===== exact fp32 refine of ALL logged candidates + epilogue =====
        const int rl = tid;
        if (rl < MTILE) {
            const long long r = row0 + rl;
            if (r < N) {
                const int cnt = scnt[rl];
                if (cnt > CAP) {
                    int ix = atomicAdd(&g_nfb, 1);
                    if (ix < FB_CAP) g_fbrows[ix] = (int)r;
                } else {
                    const float4* zr = (const float4*)(latents + r * DIMS);
                    float4 z[DIMS / 4];
                    float zn = 0.f;
                    #pragma unroll
                    for (int i = 0; i < DIMS / 4; ++i) {
                        z[i] = zr[i];
                        zn = fmaf(z[i].x, z[i].x, zn); zn = fmaf(z[i].y, z[i].y, zn);
                        zn = fmaf(z[i].z, z[i].z, zn); zn = fmaf(z[i].w, z[i].w, zn);
                    }
                    float bd = 3.402823466e38f; int be = NEMB;
                    for (int c = 0; c < cnt; ++c) {
                        const int ie = sce[rl * CAP + c];
                        const float4* wp = (const float4*)(g_Wtf + (size_t)ie * DIMS);
                        float a = 0.f;
                        #pragma unroll
                        for (int i = 0; i < DIMS / 4; ++i) {
                            float4 p = wp[i];
                            a = fmaf(z[i].x, p.x, a); a = fmaf(z[i].y, p.y, a);
                            a = fmaf(z[i].z, p.z, a); a = fmaf(z[i].w, p.w, a);
                        }
                        float d = (zn - 2.f * a) + __ldg(&g_wnorm[ie]); // exact ref
                        if (d < bd || (d == bd && ie < be)) { bd = d; be = ie; }
                    }
                    const float4* wq = (const float4*)(g_Wtf + (size_t)be * DIMS);
                    float4* oz = (float4*)(out + r * DIMS);
                    #pragma unroll
                    for (int i = 0; i < DIMS / 4; ++i) {
                        float4 w = wq[i];
                        float q0 = w.x - z[i].x, q1 = w.y - z[i].y;
                        float q2 = w.z - z[i].z, q3 = w.w - z[i].w;
                        lacc += q0*q0 + q1*q1 + q2*q2 + q3*q3;
                        oz[i] = make_float4(z[i].x + q0, z[i].y + q1,
                                            z[i].z + q2, z[i].w + q3);
                    }
                    out[(long long)N * DIMS + 2LL * N + 1 + r] = (float)be;
                }
                out[(long long)N * DIMS + r]     = scaler[r];
                out[(long long)N * DIMS + N + r] = redshift[r];
            }
        }
    }

    // ---- final block loss reduction (once) ----
    #pragma unroll
    for (int o = 16; o > 0; o >>= 1)
        lacc += __shfl_down_sync(0xffffffffu, lacc, o);
    float* wsum = (float*)(smem + SM_WSUM);
    __syncthreads();
    if (lane == 0) wsum[wid] = lacc;
    __syncthreads();
    if (tid == 0) {
        float t = 0.f;
        #pragma unroll
        for (int w = 0; w < TPB / 32; ++w) t += wsum[w];
        atomicAdd(&g_loss, (double)t);
    }
}

// ============================================================================
// fallback: exact fp32 full scan (one warp per row); expected ~0 rows
// ============================================================================
__global__ void fb_kernel(const float* __restrict__ latents,
                          float* __restrict__ out, int N)
{
    __shared__ float zbuf[4][DIMS];
    const int lane = threadIdx.x & 31, w = threadIdx.x >> 5;
    const int warps = (gridDim.x * blockDim.x) >> 5;
    const int gw = (blockIdx.x * blockDim.x + threadIdx.x) >> 5;
    const int nfb = min(g_nfb, FB_CAP);

    for (int i = gw; i < nfb; i += warps) {
        const long long row = g_fbrows[i];
        zbuf[w][2*lane]     = latents[row * DIMS + 2*lane];
        zbuf[w][2*lane + 1] = latents[row * DIMS + 2*lane + 1];
        __syncwarp();
        float zp = zbuf[w][2*lane] * zbuf[w][2*lane]
                 + zbuf[w][2*lane+1] * zbuf[w][2*lane+1];
        #pragma unroll
        for (int o = 16; o > 0; o >>= 1) zp += __shfl_down_sync(0xffffffffu, zp, o);
        float zn = __shfl_sync(0xffffffffu, zp, 0);

        const float4* z4 = (const float4*)zbuf[w];
        float bd = 3.4e38f; int be = NEMB;
        for (int e = lane; e < NEMB; e += 32) {
            const float4* wp = (const float4*)(g_Wtf + (size_t)e * DIMS);
            float a = 0.f;
            #pragma unroll
            for (int k = 0; k < DIMS / 4; ++k) {
                float4 zv = z4[k], p = wp[k];
                a = fmaf(zv.x,p.x,a); a = fmaf(zv.y,p.y,a);
                a = fmaf(zv.z,p.z,a); a = fmaf(zv.w,p.w,a);
            }
            float d = (zn - 2.f * a) + g_wnorm[e];
            if (d < bd || (d == bd && e < be)) { bd = d; be = e; }
        }
        #pragma unroll
        for (int o = 16; o > 0; o >>= 1) {
            float od = __shfl_down_sync(0xffffffffu, bd, o);
            int   oe = __shfl_down_sync(0xffffffffu, be, o);
            if (od < bd || (od == bd && oe < be)) { bd = od; be = oe; }
        }
        be = __shfl_sync(0xffffffffu, be, 0);

        float l = 0.f;
        #pragma unroll
        for (int k = 0; k < 2; ++k) {
            int d = 2*lane + k;
            float zv = zbuf[w][d];
            float wv = g_Wtf[(size_t)be * DIMS + d];
            float df = wv - zv;
            l += df * df;
            out[row * DIMS + d] = zv + df;
        }
        #pragma unroll
        for (int o = 16; o > 0; o >>= 1) l += __shfl_down_sync(0xffffffffu, l, o);
        if (lane == 0) {
            atomicAdd(&g_loss, (double)l);
            out[(long long)N * DIMS + 2LL * N + 1 + row] = (float)be;
        }
        __syncwarp();
    }
}

__global__ void finalize_kernel(float* __restrict__ out, long long off, double scale) {
    out[off] = (float)(g_loss * scale);
}

// ============================================================================
extern "C" void kernel_launch(void* const* d_in, const int* in_sizes, int n_in,
                              void* d_out, int out_size) {
    const float* latents  = (const float*)d_in[0];
    const float* scaler   = (const float*)d_in[1];
    const float* redshift = (const float*)d_in[2];
    const float* W        = (const float*)d_in[3];
    float* out = (float*)d_out;
    const int N = in_sizes[1];

    cudaFuncSetAttribute(vq_kernel, cudaFuncAttributeMaxDynamicSharedMemorySize,
                         SM_TOTAL);

    int ntiles = (N + MTILE - 1) / MTILE;
    int grid = ntiles < NCTAS ? ntiles : NCTAS;

    prep_kernel<<<(NEMB + 255) / 256, 256>>>(W);
    vq_kernel<<<grid, TPB, SM_TOTAL>>>(latents, scaler, redshift, out, N);
    fb_kernel<<<128, 128>>>(latents, out, N);
    finalize_kernel<<<1, 1>>>(out, (long long)N * DIMS + 2LL * N,
                              1.25 / ((double)N * (double)DIMS));
}

// round 17
// speedup vs baseline: 1.1743x; 1.1743x over previous
#include <cuda_runtime.h>
#include <cuda_fp16.h>
#include <cstdint>

// ============================================================================
// LatentQuantizer: persistent-CTA two-pass fp16 HMMA distance GEMM.
// Split mapping: each warp owns 32 rows (2 m-tiles) x HALF the codebook, so
// per-warp B smem traffic halves vs R14 while tiles stay 256 rows (tiny tail).
// Pass 1: branchless max-dot, merged across warp pairs via smem.
// Pass 2: branch-cold threshold push (d > D - c), CAP=8.
// Exact fp32 lexicographic refine; rare overflow -> full fp32 fallback.
// Inputs: latents [N*64] f32, scaler [N] f32, redshift [N] f32,
//         codebook_weight [64*1024] f32 (D-major).
// Output f32: z_q_st [N*64], scaler [N], redshift [N], loss [1], ids [N]
// ============================================================================

#define DIMS   64
#define NEMB   1024
#define HALFE  512          // codes per warp-half
#define MTILE  256          // rows per tile
#define TPB    512          // 16 warps: 8 row-groups x 2 code-halves
#define CAP    8            // candidate index slots per row
#define NCTAS  148          // persistent grid (1 CTA/SM)

// dynamic smem layout (bytes)
#define SM_B     0                           // 1024 x 128B fp16 swizzled (resident)
#define SM_A     (SM_B + NEMB * 128)         // 131072: 256 x 128B
#define SM_ZN    (SM_A + MTILE * 128)        // 163840: 256 f32
#define SM_SD    (SM_ZN + MTILE * 4)         // 164864: 2 x 256 f32 (half-maxes)
#define SM_CE    (SM_SD + 2 * MTILE * 4)     // 166912: 256 x CAP ints
#define SM_CNT   (SM_CE + MTILE * CAP * 4)   // 175104: 256 ints
#define SM_WSUM  (SM_CNT + MTILE * 4)        // 176128: 16 f32
#define SM_TOTAL (SM_WSUM + 64)              // 176192

#define FB_CAP (1 << 19)

// -------------------- device scratch (no allocations) -----------------------
__device__ __align__(16)   float  g_Wtf[NEMB * DIMS];   // e-major fp32
__device__ __align__(1024) __half g_Wth[NEMB * DIMS];   // e-major fp16, swizzled
__device__ float  g_wnorm[NEMB];
__device__ int    g_wmaxbits = 0;
__device__ int    g_wminbits = 0x7f7fffff;
__device__ double g_loss;
__device__ int    g_nfb;
__device__ int    g_fbrows[FB_CAP];

__device__ __forceinline__ uint32_t sw128(uint32_t o) { return o ^ ((o >> 3) & 0x70); }

__device__ __forceinline__ uint32_t smem_u32(const void* p) {
    uint32_t a;
    asm("{ .reg .u64 t; cvta.to.shared.u64 t, %1; cvt.u32.u64 %0, t; }"
        : "=r"(a) : "l"(p));
    return a;
}

#define LDSM_X4(r, addr)                                                     \
    asm volatile("ldmatrix.sync.aligned.m8n8.x4.shared.b16 {%0,%1,%2,%3}, [%4];" \
        : "=r"((r)[0]), "=r"((r)[1]), "=r"((r)[2]), "=r"((r)[3])             \
        : "r"(addr))

__device__ __forceinline__ void mma16816(float* d, const uint32_t* a,
                                         const uint32_t* b) {
    asm volatile(
        "mma.sync.aligned.m16n8k16.row.col.f32.f16.f16.f32 "
        "{%0,%1,%2,%3}, {%4,%5,%6,%7}, {%8,%9}, {%0,%1,%2,%3};"
        : "+f"(d[0]), "+f"(d[1]), "+f"(d[2]), "+f"(d[3])
        : "r"(a[0]), "r"(a[1]), "r"(a[2]), "r"(a[3]), "r"(b[0]), "r"(b[1]));
}

// ============================================================================
// prep: wnorm + min/max, fp32 transpose, swizzled fp16 transpose, zero accums
// ============================================================================
__global__ void prep_kernel(const float* __restrict__ W) {
    int e = blockIdx.x * blockDim.x + threadIdx.x;
    if (blockIdx.x == 0 && threadIdx.x == 0) { g_loss = 0.0; g_nfb = 0; }
    if (e >= NEMB) return;
    float col[DIMS];
    float s = 0.f;
    #pragma unroll
    for (int d = 0; d < DIMS; ++d) {
        float v = W[d * NEMB + e];
        col[d] = v;
        s = fmaf(v, v, s);
    }
    g_wnorm[e] = s;
    atomicMax(&g_wmaxbits, __float_as_int(s));   // s > 0: int order == float
    atomicMin(&g_wminbits, __float_as_int(s));
    float4* dst = (float4*)(g_Wtf + (size_t)e * DIMS);
    #pragma unroll
    for (int i = 0; i < DIMS / 4; ++i)
        dst[i] = make_float4(col[4*i], col[4*i+1], col[4*i+2], col[4*i+3]);
    char* bb = (char*)g_Wth;
    #pragma unroll
    for (int k = 0; k < DIMS; k += 2) {
        __half2 p = __floats2half2_rn(col[k], col[k + 1]);
        uint32_t bo = (uint32_t)e * 128u + (uint32_t)k * 2u;
        *(uint32_t*)(bb + sw128(bo)) = *(uint32_t*)&p;
    }
}

// ============================================================================
// vq: persistent CTAs; B resident; warp = 32 rows x half codebook.
// ============================================================================
__global__ __launch_bounds__(TPB, 1) void vq_kernel(
    const float* __restrict__ latents,
    const float* __restrict__ scaler,
    const float* __restrict__ redshift,
    float* __restrict__ out,
    int N)
{
    extern __shared__ char smem[];
    const uint32_t sb = smem_u32(smem);
    const int tid = threadIdx.x, wid = tid >> 5, lane = tid & 31;
    const int rgrp = wid & 7;                // row group: rows rgrp*32..+32
    const int half = wid >> 3;               // code half: [half*512, +512)
    const int wb = rgrp * 32;

    float* szn  = (float*)(smem + SM_ZN);
    float* sD   = (float*)(smem + SM_SD);    // [2][MTILE]
    int*   sce  = (int*)(smem + SM_CE);
    int*   scnt = (int*)(smem + SM_CNT);

    // ---- B: full fp16 codebook -> smem ONCE (pre-swizzled, raw copy) ----
    {
        const float4* src = (const float4*)g_Wth;
        float4* dst = (float4*)(smem + SM_B);
        #pragma unroll 8
        for (int i = tid; i < NEMB * 128 / 16; i += TPB) dst[i] = src[i];
    }

    const float wmax = __int_as_float(g_wmaxbits);
    const float wrange = wmax - __int_as_float(g_wminbits);

    const uint32_t brow = sb + SM_B + (lane & 7) * 128;
    const uint32_t bx1  = (((lane >> 3) ^ (lane & 7)) << 4);
    const uint32_t bx2  = ((((lane >> 3) + 4) ^ (lane & 7)) << 4);
    const int cbase = half * HALFE + (lane & 3) * 2;

    const int ntiles = (N + MTILE - 1) / MTILE;
    float lacc = 0.f;                        // per-thread loss across tiles

    for (int tile = blockIdx.x; tile < ntiles; tile += gridDim.x) {
        const long long row0 = (long long)tile * MTILE;
        __syncthreads();                     // prior tile epilogue done

        // ---- per-tile prologue: reset counters, A convert + ||z||^2 ----
        for (int i = tid; i < MTILE; i += TPB) scnt[i] = 0;
        for (int i = tid; i < MTILE * 32; i += TPB) {
            int r = i >> 5, kp = i & 31;     // whole warp shares r
            long long gr = row0 + r;
            float2 z2 = (gr < N) ? ((const float2*)latents)[gr * 32 + kp]
                                 : make_float2(0.f, 0.f);
            __half2 p = __floats2half2_rn(z2.x, z2.y);
            *(uint32_t*)(smem + SM_A + sw128((uint32_t)r * 128u + (uint32_t)kp * 4u))
                = *(uint32_t*)&p;
            float zp = fmaf(z2.x, z2.x, z2.y * z2.y);
            #pragma unroll
            for (int o = 16; o > 0; o >>= 1)
                zp += __shfl_down_sync(0xffffffffu, zp, o);
            if (lane == 0) szn[r] = zp;
        }
        __syncthreads();

        // ---- A fragments: 2 m16 tiles x 4 k16 steps (32 regs) ----
        uint32_t afrag[2][4][4];
        {
            int row = wb + ((lane >> 3) & 1) * 8 + (lane & 7);
            #pragma unroll
            for (int mt = 0; mt < 2; ++mt) {
                int rr = row + mt * 16;
                #pragma unroll
                for (int ks = 0; ks < 4; ++ks) {
                    int kb = ks * 2 + (lane >> 4);
                    uint32_t ad = sb + SM_A + rr * 128 + ((kb ^ (rr & 7)) << 4);
                    LDSM_X4(afrag[mt][ks], ad);
                }
            }
        }

        // ========= pass 1: running max dot over this warp's half =========
        float D0 = -3.402823466e38f, D1 = D0, D2 = D0, D3 = D0;
        #pragma unroll 2
        for (int nt = 0; nt < HALFE / 8; ++nt) {
            const int n0 = half * HALFE + nt * 8;     // global code index
            uint32_t b[8];
            LDSM_X4(b,     brow + n0 * 128 + bx1);
            LDSM_X4(b + 4, brow + n0 * 128 + bx2);
            float d0[4] = {0.f, 0.f, 0.f, 0.f};
            float d1[4] = {0.f, 0.f, 0.f, 0.f};
            #pragma unroll
            for (int ks = 0; ks < 4; ++ks) {
                mma16816(d0, afrag[0][ks], b + 2 * ks);
                mma16816(d1, afrag[1][ks], b + 2 * ks);
            }
            D0 = fmaxf(D0, fmaxf(d0[0], d0[1]));
            D1 = fmaxf(D1, fmaxf(d0[2], d0[3]));
            D2 = fmaxf(D2, fmaxf(d1[0], d1[1]));
            D3 = fmaxf(D3, fmaxf(d1[2], d1[3]));
        }
        // quad merge (4 lanes sharing each row)
        D0 = fmaxf(D0, __shfl_xor_sync(0xffffffffu, D0, 1));
        D0 = fmaxf(D0, __shfl_xor_sync(0xffffffffu, D0, 2));
        D1 = fmaxf(D1, __shfl_xor_sync(0xffffffffu, D1, 1));
        D1 = fmaxf(D1, __shfl_xor_sync(0xffffffffu, D1, 2));
        D2 = fmaxf(D2, __shfl_xor_sync(0xffffffffu, D2, 1));
        D2 = fmaxf(D2, __shfl_xor_sync(0xffffffffu, D2, 2));
        D3 = fmaxf(D3, __shfl_xor_sync(0xffffffffu, D3, 1));
        D3 = fmaxf(D3, __shfl_xor_sync(0xffffffffu, D3, 2));

        // cross-half merge via smem: sD[half][row]
        const int rl0 = wb + (lane >> 2);
        const int rl1 = rl0 + 8, rl2 = rl0 + 16, rl3 = rl0 + 24;
        if ((lane & 3) == 0) {
            sD[half * MTILE + rl0] = D0;
            sD[half * MTILE + rl1] = D1;
            sD[half * MTILE + rl2] = D2;
            sD[half * MTILE + rl3] = D3;
        }
        __syncthreads();
        D0 = fmaxf(sD[rl0], sD[MTILE + rl0]);
        D1 = fmaxf(sD[rl1], sD[MTILE + rl1]);
        D2 = fmaxf(sD[rl2], sD[MTILE + rl2]);
        D3 = fmaxf(sD[rl3], sD[MTILE + rl3]);

        // thresholds: t = D - 0.5*(wrange + 2^-8*sqrt(zn*wmax) + slack)
        const float t0 = D0 - 0.5f * (wrange + 0.00390625f * sqrtf(szn[rl0] * wmax) + 1e-4f);
        const float t1 = D1 - 0.5f * (wrange + 0.00390625f * sqrtf(szn[rl1] * wmax) + 1e-4f);
        const float t2 = D2 - 0.5f * (wrange + 0.00390625f * sqrtf(szn[rl2] * wmax) + 1e-4f);
        const float t3 = D3 - 0.5f * (wrange + 0.00390625f * sqrtf(szn[rl3] * wmax) + 1e-4f);

        // ========= pass 2: branch-cold candidate pushes (this half) =========
#define PUSH(RL, E) do {                                                      \
            int _s = atomicAdd(&scnt[RL], 1);                                 \
            if (_s < CAP) sce[(RL) * CAP + _s] = (E);                         \
        } while (0)
#define STEP2(SA, SB, T, RL, C0, C1) do {                                     \
            if (fmaxf(SA, SB) > (T)) {                                        \
                if ((SA) > (T)) PUSH(RL, C0);                                 \
                if ((SB) > (T)) PUSH(RL, C1);                                 \
            }                                                                 \
        } while (0)

        #pragma unroll 2
        for (int nt = 0; nt < HALFE / 8; ++nt) {
            const int n0 = half * HALFE + nt * 8;
            uint32_t b[8];
            LDSM_X4(b,     brow + n0 * 128 + bx1);
            LDSM_X4(b + 4, brow + n0 * 128 + bx2);
            float d0[4] = {0.f, 0.f, 0.f, 0.f};
            float d1[4] = {0.f, 0.f, 0.f, 0.f};
            #pragma unroll
            for (int ks = 0; ks < 4; ++ks) {
                mma16816(d0, afrag[0][ks], b + 2 * ks);
                mma16816(d1, afrag[1][ks], b + 2 * ks);
            }
            const int c0 = nt * 8 + cbase, c1 = c0 + 1;
            STEP2(d0[0], d0[1], t0, rl0, c0, c1);
            STEP2(d0[2], d0[3], t1, rl1, c0, c1);
            STEP2(d1[0], d1[1], t2, rl2, c0, c1);
            STEP2(d1[2], d1[3], t3, rl3, c0, c1);
        }
#undef STEP2
#undef PUSH
        __syncthreads();

        // ===== exact fp32 refine of ALL logged candidates + epilogue =====
        const int rl = tid;
        if (rl < MTILE) {
            const long long r = row0 + rl;
            if (r < N) {
                const int cnt = scnt[rl];
                if (cnt > CAP) {
                    int ix = atomicAdd(&g_nfb, 1);
                    if (ix < FB_CAP) g_fbrows[ix] = (int)r;
                } else {
                    const float4* zr = (const float4*)(latents + r * DIMS);
                    float4 z[DIMS / 4];
                    float zn = 0.f;
                    #pragma unroll
                    for (int i = 0; i < DIMS / 4; ++i) {
                        z[i] = zr[i];
                        zn = fmaf(z[i].x, z[i].x, zn); zn = fmaf(z[i].y, z[i].y, zn);
                        zn = fmaf(z[i].z, z[i].z, zn); zn = fmaf(z[i].w, z[i].w, zn);
                    }
                    float bd = 3.402823466e38f; int be = NEMB;
                    for (int c = 0; c < cnt; ++c) {
                        const int ie = sce[rl * CAP + c];
                        const float4* wp = (const float4*)(g_Wtf + (size_t)ie * DIMS);
                        float a = 0.f;
                        #pragma unroll
                        for (int i = 0; i < DIMS / 4; ++i) {
                            float4 p = wp[i];
                            a = fmaf(z[i].x, p.x, a); a = fmaf(z[i].y, p.y, a);
                            a = fmaf(z[i].z, p.z, a); a = fmaf(z[i].w, p.w, a);
                        }
                        float d = (zn - 2.f * a) + __ldg(&g_wnorm[ie]); // exact ref
                        if (d < bd || (d == bd && ie < be)) { bd = d; be = ie; }
                    }
                    const float4* wq = (const float4*)(g_Wtf + (size_t)be * DIMS);
                    float4* oz = (float4*)(out + r * DIMS);
                    #pragma unroll
                    for (int i = 0; i < DIMS / 4; ++i) {
                        float4 w = wq[i];
                        float q0 = w.x - z[i].x, q1 = w.y - z[i].y;
                        float q2 = w.z - z[i].z, q3 = w.w - z[i].w;
                        lacc += q0*q0 + q1*q1 + q2*q2 + q3*q3;
                        oz[i] = make_float4(z[i].x + q0, z[i].y + q1,
                                            z[i].z + q2, z[i].w + q3);
                    }
                    out[(long long)N * DIMS + 2LL * N + 1 + r] = (float)be;
                }
                out[(long long)N * DIMS + r]     = scaler[r];
                out[(long long)N * DIMS + N + r] = redshift[r];
            }
        }
    }

    // ---- final block loss reduction (once) ----
    #pragma unroll
    for (int o = 16; o > 0; o >>= 1)
        lacc += __shfl_down_sync(0xffffffffu, lacc, o);
    float* wsum = (float*)(smem + SM_WSUM);
    __syncthreads();
    if (lane == 0) wsum[wid] = lacc;
    __syncthreads();
    if (tid == 0) {
        float t = 0.f;
        #pragma unroll
        for (int w = 0; w < TPB / 32; ++w) t += wsum[w];
        atomicAdd(&g_loss, (double)t);
    }
}

// ============================================================================
// fallback: exact fp32 full scan (one warp per row); expected ~0 rows
// ============================================================================
__global__ void fb_kernel(const float* __restrict__ latents,
                          float* __restrict__ out, int N)
{
    __shared__ float zbuf[4][DIMS];
    const int lane = threadIdx.x & 31, w = threadIdx.x >> 5;
    const int warps = (gridDim.x * blockDim.x) >> 5;
    const int gw = (blockIdx.x * blockDim.x + threadIdx.x) >> 5;
    const int nfb = min(g_nfb, FB_CAP);

    for (int i = gw; i < nfb; i += warps) {
        const long long row = g_fbrows[i];
        zbuf[w][2*lane]     = latents[row * DIMS + 2*lane];
        zbuf[w][2*lane + 1] = latents[row * DIMS + 2*lane + 1];
        __syncwarp();
        float zp = zbuf[w][2*lane] * zbuf[w][2*lane]
                 + zbuf[w][2*lane+1] * zbuf[w][2*lane+1];
        #pragma unroll
        for (int o = 16; o > 0; o >>= 1) zp += __shfl_down_sync(0xffffffffu, zp, o);
        float zn = __shfl_sync(0xffffffffu, zp, 0);

        const float4* z4 = (const float4*)zbuf[w];
        float bd = 3.4e38f; int be = NEMB;
        for (int e = lane; e < NEMB; e += 32) {
            const float4* wp = (const float4*)(g_Wtf + (size_t)e * DIMS);
            float a = 0.f;
            #pragma unroll
            for (int k = 0; k < DIMS / 4; ++k) {
                float4 zv = z4[k], p = wp[k];
                a = fmaf(zv.x,p.x,a); a = fmaf(zv.y,p.y,a);
                a = fmaf(zv.z,p.z,a); a = fmaf(zv.w,p.w,a);
            }
            float d = (zn - 2.f * a) + g_wnorm[e];
            if (d < bd || (d == bd && e < be)) { bd = d; be = e; }
        }
        #pragma unroll
        for (int o = 16; o > 0; o >>= 1) {
            float od = __shfl_down_sync(0xffffffffu, bd, o);
            int   oe = __shfl_down_sync(0xffffffffu, be, o);
            if (od < bd || (od == bd && oe < be)) { bd = od; be = oe; }
        }
        be = __shfl_sync(0xffffffffu, be, 0);

        float l = 0.f;
        #pragma unroll
        for (int k = 0; k < 2; ++k) {
            int d = 2*lane + k;
            float zv = zbuf[w][d];
            float wv = g_Wtf[(size_t)be * DIMS + d];
            float df = wv - zv;
            l += df * df;
            out[row * DIMS + d] = zv + df;
        }
        #pragma unroll
        for (int o = 16; o > 0; o >>= 1) l += __shfl_down_sync(0xffffffffu, l, o);
        if (lane == 0) {
            atomicAdd(&g_loss, (double)l);
            out[(long long)N * DIMS + 2LL * N + 1 + row] = (float)be;
        }
        __syncwarp();
    }
}

__global__ void finalize_kernel(float* __restrict__ out, long long off, double scale) {
    out[off] = (float)(g_loss * scale);
}

// ============================================================================
extern "C" void kernel_launch(void* const* d_in, const int* in_sizes, int n_in,
                              void* d_out, int out_size) {
    const float* latents  = (const float*)d_in[0];
    const float* scaler   = (const float*)d_in[1];
    const float* redshift = (const float*)d_in[2];
    const float* W        = (const float*)d_in[3];
    float* out = (float*)d_out;
    const int N = in_sizes[1];

    cudaFuncSetAttribute(vq_kernel, cudaFuncAttributeMaxDynamicSharedMemorySize,
                         SM_TOTAL);

    int ntiles = (N + MTILE - 1) / MTILE;
    int grid = ntiles < NCTAS ? ntiles : NCTAS;

    prep_kernel<<<(NEMB + 255) / 256, 256>>>(W);
    vq_kernel<<<grid, TPB, SM_TOTAL>>>(latents, scaler, redshift, out, N);
    fb_kernel<<<128, 128>>>(latents, out, N);
    finalize_kernel<<<1, 1>>>(out, (long long)N * DIMS + 2LL * N,
                              1.25 / ((double)N * (double)DIMS));
}